// round 14
// baseline (speedup 1.0000x reference)
#include <cuda_runtime.h>
#include <cuda_fp16.h>
#include <math.h>
#include <stdint.h>

#define BB 8
#define SS 4096
#define HH 768
#define MS 64
#define F1 4096
#define F2 256
#define SEPTOK 2
#define MROWS 512          // BB*MS
#define NSPLIT 16
#define CHUNK_T 8                           // tokens per bulk chunk
#define CHUNK_BYTES (CHUNK_T * HH * 4)      // 24576
#define NBUF 2                              // pool smem ring depth (48KB/CTA -> 4 CTA/SM)

// ---------------- scratch (device globals; no allocation allowed) ----------
__device__ __align__(1024) __half g_sentb[MROWS * HH];    // A GEMM1, fp16
__device__ __align__(1024) __half g_w1b[F1 * HH];         // B GEMM1: W1^T fp16
__device__ __align__(1024) __half g_x1b[MROWS * F1];      // A GEMM2, fp16
__device__ __align__(1024) __half g_w2b[F2 * F1];         // B GEMM2: W2^T fp16
__device__ __align__(1024) float g_x2p[NSPLIT * MROWS * F2];   // split-K partials
__device__ int   g_sep_pos[BB][SS];
__device__ int   g_nsep[BB];

__device__ __forceinline__ float gelu_exact(float x) {
    return 0.5f * x * (1.0f + erff(x * 0.70710678118654752f));
}

__device__ __forceinline__ uint32_t smem_u32(const void* p) {
    uint32_t a;
    asm("{ .reg .u64 t; cvta.to.shared.u64 t, %1; cvt.u32.u64 %0, t; }" : "=r"(a) : "l"(p));
    return a;
}
__device__ __forceinline__ uint32_t sw128(uint32_t off) {
    return off ^ ((off >> 3) & 0x70);
}
__device__ __forceinline__ void cp_async16(uint32_t dst, const void* src) {
    asm volatile("cp.async.cg.shared.global [%0], [%1], 16;" :: "r"(dst), "l"(src) : "memory");
}
__device__ __forceinline__ void cp_commit() {
    asm volatile("cp.async.commit_group;" ::: "memory");
}
template<int N>
__device__ __forceinline__ void cp_waitg() {
    asm volatile("cp.async.wait_group %0;" :: "n"(N) : "memory");
}
__device__ __forceinline__ void ldsm_x4(uint32_t* r, uint32_t addr) {
    asm volatile("ldmatrix.sync.aligned.m8n8.x4.shared.b16 {%0,%1,%2,%3}, [%4];"
                 : "=r"(r[0]), "=r"(r[1]), "=r"(r[2]), "=r"(r[3]) : "r"(addr));
}
__device__ __forceinline__ void mma16816(float* d, const uint32_t* a, const uint32_t* b) {
    asm volatile(
        "mma.sync.aligned.m16n8k16.row.col.f32.f16.f16.f32 "
        "{%0,%1,%2,%3}, {%4,%5,%6,%7}, {%8,%9}, {%0,%1,%2,%3};"
        : "+f"(d[0]), "+f"(d[1]), "+f"(d[2]), "+f"(d[3])
        : "r"(a[0]), "r"(a[1]), "r"(a[2]), "r"(a[3]), "r"(b[0]), "r"(b[1]));
}

#define MBAR_INIT(a, c) \
    asm volatile("mbarrier.init.shared.b64 [%0], %1;" :: "r"(a), "r"(c) : "memory")
#define MBAR_EXPECT_TX(a, bytes) \
    asm volatile("mbarrier.arrive.expect_tx.shared.b64 _, [%0], %1;" :: "r"(a), "r"(bytes) : "memory")
#define MBAR_WAIT(mb, par) do {                                                        \
    uint32_t _m = (mb), _p = (par), _d;                                                \
    asm volatile("{\n\t.reg .pred p;\n\t"                                              \
        "mbarrier.try_wait.parity.acquire.cta.shared::cta.b64 p, [%1], %2;\n\t"        \
        "selp.b32 %0, 1, 0, p;\n\t}" : "=r"(_d) : "r"(_m), "r"(_p) : "memory");        \
    if (!_d) {                                                                         \
        asm volatile("{\n\t.reg .pred P1;\n\t"                                         \
            "WAIT_LOOP_%=:\n\t"                                                        \
            "mbarrier.try_wait.parity.acquire.cta.shared::cta.b64 P1, [%0], %1, 0x989680;\n\t" \
            "@P1 bra.uni WAIT_DONE_%=;\n\t"                                            \
            "bra.uni WAIT_LOOP_%=;\n\t"                                                \
            "WAIT_DONE_%=:\n\t}" :: "r"(_m), "r"(_p) : "memory");                      \
    }                                                                                  \
} while (0)

// segment bounds (reference semantics)
__device__ __forceinline__ void seg_bounds(int b, int s, int& t0, int& t1) {
    const int n = g_nsep[b];
    t0 = 0; t1 = 0;
    if (n == 0) {
        if (s == 0) { t0 = 0; t1 = SS; }
    } else if (s < n) {
        if (s == 0) { t0 = 0; t1 = g_sep_pos[b][0] + 1; }
        else        { t0 = g_sep_pos[b][s - 1] + 1; t1 = g_sep_pos[b][s]; }
    } else if (s == n) {
        t0 = g_sep_pos[b][n - 1] + 1; t1 = SS - 1;
    }
}

// ---------------- 1) sep scan (shuffle block scan) --------------------------
__global__ void sep_scan_kernel(const int* __restrict__ ids32) {
    const int b = blockIdx.x;
    const int tid = threadIdx.x;                  // 256
    const int stride = (ids32[1] == 0) ? 2 : 1;   // int64 vs int32 auto-detect
    const int* row = ids32 + (size_t)b * SS * stride;

    const int base = tid * 16;
    int c = 0;
    #pragma unroll
    for (int i = 0; i < 16; i++)
        if (row[(base + i) * stride] == SEPTOK) c++;

    const int lane = tid & 31, w = tid >> 5;
    int incl = c;
    #pragma unroll
    for (int o = 1; o < 32; o <<= 1) {
        int t = __shfl_up_sync(0xffffffffu, incl, o);
        if (lane >= o) incl += t;
    }
    __shared__ int wsum[8], woff[8];
    if (lane == 31) wsum[w] = incl;
    __syncthreads();
    if (tid == 0) {
        int a = 0;
        #pragma unroll
        for (int i = 0; i < 8; i++) { woff[i] = a; a += wsum[i]; }
        g_nsep[b] = a;
    }
    __syncthreads();

    int off = woff[w] + incl - c;
    for (int i = 0; i < 16; i++)
        if (row[(base + i) * stride] == SEPTOK)
            g_sep_pos[b][off++] = base + i;
}

// ---------------- 2) pooling via cp.async.bulk (TMA path), single wave ------
__global__ void pool_kernel(const float* __restrict__ hidden) {
    const int s   = blockIdx.x;   // 0..63
    const int b   = blockIdx.y;   // 0..7
    const int tid = threadIdx.x;  // 192 (= HH/4)

    extern __shared__ __align__(16) char psm[];       // NBUF x CHUNK_BYTES
    __shared__ __align__(8) uint64_t mbar[NBUF];

    int t0, t1;
    seg_bounds(b, s, t0, t1);
    const int len = t1 - t0;
    const int nc  = (len + CHUNK_T - 1) / CHUNK_T;

    const uint32_t smBase = smem_u32(psm);
    const uint32_t mb     = smem_u32(&mbar[0]);

    if (tid < NBUF) MBAR_INIT(mb + tid * 8, 1);
    __syncthreads();

    const float* src0 = hidden + (size_t)b * SS * HH + (size_t)t0 * HH;

    auto issue = [&](int i) {   // tid==0 only
        const int ct = min(CHUNK_T, len - i * CHUNK_T);
        const uint32_t bytes = (uint32_t)ct * HH * 4;
        const int bi = i & (NBUF - 1);
        const uint32_t mbi = mb + (uint32_t)(bi * 8);
        MBAR_EXPECT_TX(mbi, bytes);
        asm volatile(
            "cp.async.bulk.shared::cluster.global.mbarrier::complete_tx::bytes "
            "[%0], [%1], %2, [%3];"
            :: "r"(smBase + (uint32_t)(bi * CHUNK_BYTES)),
               "l"(src0 + (size_t)i * CHUNK_T * HH), "r"(bytes), "r"(mbi)
            : "memory");
    };

    if (tid == 0) {
        #pragma unroll
        for (int i = 0; i < NBUF; i++)
            if (i < nc) issue(i);
    }

    float4 acc = make_float4(0.f, 0.f, 0.f, 0.f);
    for (int i = 0; i < nc; i++) {
        MBAR_WAIT(mb + (i & (NBUF - 1)) * 8, (i / NBUF) & 1);
        const int ct = min(CHUNK_T, len - i * CHUNK_T);
        const float4* buf = (const float4*)(psm + (i & (NBUF - 1)) * CHUNK_BYTES);
        for (int t = 0; t < ct; t++) {
            float4 v = buf[t * 192 + tid];
            acc.x += v.x; acc.y += v.y; acc.z += v.z; acc.w += v.w;
        }
        __syncthreads();                       // buffer free for reuse
        if (tid == 0 && i + NBUF < nc) issue(i + NBUF);
    }

    const float inv = (len > 0) ? (1.0f / (float)len) : 0.0f;
    const size_t rb = (size_t)(b * MS + s) * HH + tid * 4;
    *(__half2*)(&g_sentb[rb]) =
        __halves2half2(__float2half(acc.x * inv), __float2half(acc.y * inv));
    *(__half2*)(&g_sentb[rb + 2]) =
        __halves2half2(__float2half(acc.z * inv), __float2half(acc.w * inv));
}

// ---------------- 3) weight transpose, fp16 -------------------------------
// W: [K, N] row-major  ->  out: [N, K] fp16
__global__ void conv_w_kernel(const float* __restrict__ W, __half* __restrict__ out,
                              int K, int N) {
    __shared__ float t[32][33];
    const int n0 = blockIdx.x * 32, k0 = blockIdx.y * 32;
    const int tx = threadIdx.x, ty = threadIdx.y;   // 32 x 8
    #pragma unroll
    for (int i = 0; i < 4; i++)
        t[ty + i * 8][tx] = W[(size_t)(k0 + ty + i * 8) * N + n0 + tx];
    __syncthreads();
    #pragma unroll
    for (int i = 0; i < 4; i++) {
        const int nn = n0 + ty + i * 8;
        out[(size_t)nn * K + k0 + tx] = __float2half(t[tx][ty + i * 8]);
    }
}

// ---------------- 4) mma.sync fp16 GEMM, 128x128 tile, K staged 128 ---------
// A: [M, lda] K-major fp16.  B: [N, ldb] K-major fp16 (B^T).
// 3-deep cp.async ring; 8 warps 4(m)x2(n), warp tile 32x64.
// EPI==1: D + bias -> GELU -> fp16 x1.  EPI==0: fp32 split-K partials.
template<int EPI>
__global__ __launch_bounds__(256)
void mma_gemm(const __half* __restrict__ A, int lda,
              const __half* __restrict__ Bm, int ldb,
              int nStages,            // number of 128-wide K stages
              const float* __restrict__ bias,
              float* __restrict__ Cout,
              __half* __restrict__ OutB)
{
    extern __shared__ char dsm_raw[];
    char* dsm = (char*)(((uintptr_t)dsm_raw + 1023) & ~(uintptr_t)1023);

    const int tid  = threadIdx.x;
    const int wid  = tid >> 5, lane = tid & 31;
    const int m0   = blockIdx.y * 128;
    const int n0   = blockIdx.x * 128;
    const int z    = blockIdx.z;
    const int ks0  = z * nStages * 128;

    const uint32_t smBase = smem_u32(dsm);

    auto load_stage = [&](int buf, int s) {
        const int ko = ks0 + s * 128;
        const uint32_t dA = smBase + buf * 32768;
        const uint32_t dB = smBase + 98304 + buf * 32768;
        #pragma unroll
        for (int sub = 0; sub < 2; sub++) {
            const __half* Ag = A  + (size_t)m0 * lda + ko + sub * 64;
            const __half* Bg = Bm + (size_t)n0 * ldb + ko + sub * 64;
            #pragma unroll
            for (int i = 0; i < 4; i++) {
                const int ch = tid + i * 256;     // 1024 16B chunks / sub-tile
                const int r = ch >> 3, c = ch & 7;
                const uint32_t sw = sw128((uint32_t)(r * 128 + c * 16)) + sub * 16384;
                cp_async16(dA + sw, Ag + (size_t)r * lda + c * 8);
                cp_async16(dB + sw, Bg + (size_t)r * ldb + c * 8);
            }
        }
    };

    // ---- warp/lane fragment geometry
    const int wm0 = (wid & 3) * 32;
    const int wn0 = (wid >> 2) * 64;
    const int grp = lane >> 3, rowin = lane & 7;
    const int a_mloc = rowin + ((grp & 1) << 3);
    const int a_koff = (grp >> 1) << 4;
    const int b_nloc = rowin + ((grp >> 1) << 3);
    const int b_koff = (grp & 1) << 4;

    float acc[2][8][4];
    #pragma unroll
    for (int mt = 0; mt < 2; mt++)
        #pragma unroll
        for (int nt = 0; nt < 8; nt++)
            #pragma unroll
            for (int q = 0; q < 4; q++) acc[mt][nt][q] = 0.f;

    load_stage(0, 0);
    cp_commit();
    if (nStages > 1) { load_stage(1, 1); cp_commit(); }

    int buf = 0;
    for (int s = 0; s < nStages; s++) {
        if (s + 1 < nStages) cp_waitg<1>(); else cp_waitg<0>();
        __syncthreads();

        #pragma unroll
        for (int sub = 0; sub < 2; sub++) {
            const uint32_t uA = smBase + buf * 32768 + sub * 16384;
            const uint32_t uB = smBase + 98304 + buf * 32768 + sub * 16384;
            const uint32_t aRow[2] = {
                uA + (uint32_t)((wm0 + a_mloc) * 128),
                uA + (uint32_t)((wm0 + 16 + a_mloc) * 128) };
            const uint32_t aXor = (uint32_t)(((wm0 + a_mloc) & 7) << 4);
            const uint32_t bXor = (uint32_t)(((wn0 + b_nloc) & 7) << 4);

            #pragma unroll
            for (int kk = 0; kk < 4; kk++) {
                uint32_t afr[2][4];
                #pragma unroll
                for (int mt = 0; mt < 2; mt++)
                    ldsm_x4(afr[mt], aRow[mt] + (((uint32_t)(kk * 32 + a_koff)) ^ aXor));

                uint32_t bfr[8][2];
                #pragma unroll
                for (int p = 0; p < 4; p++) {
                    uint32_t r4[4];
                    const uint32_t bRow = uB + (uint32_t)((wn0 + p * 16 + b_nloc) * 128);
                    ldsm_x4(r4, bRow + (((uint32_t)(kk * 32 + b_koff)) ^ bXor));
                    bfr[2 * p][0] = r4[0]; bfr[2 * p][1] = r4[1];
                    bfr[2 * p + 1][0] = r4[2]; bfr[2 * p + 1][1] = r4[3];
                }

                #pragma unroll
                for (int mt = 0; mt < 2; mt++)
                    #pragma unroll
                    for (int nt = 0; nt < 8; nt++)
                        mma16816(acc[mt][nt], afr[mt], bfr[nt]);
            }
        }

        // 3-buffer ring: overwrite target was consumed at stage s-1; the
        // top-of-loop barrier for stage s already fenced all its readers.
        if (s + 2 < nStages) { load_stage((s + 2) % 3, s + 2); cp_commit(); }
        buf = (buf + 1) % 3;
    }

    // ---- epilogue
    #pragma unroll
    for (int mt = 0; mt < 2; mt++) {
        const int rA = m0 + wm0 + mt * 16 + (lane >> 2);
        #pragma unroll
        for (int half = 0; half < 2; half++) {
            const int r = rA + half * 8;
            if (EPI == 1) {
                const size_t rowbase = (size_t)r * F1;
                #pragma unroll
                for (int nt = 0; nt < 8; nt++) {
                    const int f = n0 + wn0 + nt * 8 + (lane & 3) * 2;
                    float v0 = gelu_exact(acc[mt][nt][2 * half]     + __ldg(&bias[f]));
                    float v1 = gelu_exact(acc[mt][nt][2 * half + 1] + __ldg(&bias[f + 1]));
                    *(__half2*)(&OutB[rowbase + f]) =
                        __halves2half2(__float2half(v0), __float2half(v1));
                }
            } else {
                float* Cp = Cout + (size_t)z * MROWS * F2 + (size_t)r * F2;
                #pragma unroll
                for (int nt = 0; nt < 8; nt++) {
                    const int f = n0 + wn0 + nt * 8 + (lane & 3) * 2;
                    float2 v; v.x = acc[mt][nt][2 * half]; v.y = acc[mt][nt][2 * half + 1];
                    *(float2*)(Cp + f) = v;
                }
            }
        }
    }
}

// ---------------- 5) fused split-K reduce + bias + GELU + head --------------
__global__ void reduce_head_kernel(const float* __restrict__ b2,
                                   const float* __restrict__ W3,
                                   const float* __restrict__ b3,
                                   float* __restrict__ out) {
    const int row = blockIdx.x;   // 512
    const int tid = threadIdx.x;  // 256
    const int idx = row * F2 + tid;
    float s = 0.f;
    #pragma unroll
    for (int i = 0; i < NSPLIT; i++) s += g_x2p[(size_t)i * MROWS * F2 + idx];
    const float x = gelu_exact(s + b2[tid]);

    __shared__ float sh0[256];
    __shared__ float sh1[256];
    sh0[tid] = x * W3[tid * 2 + 0];
    sh1[tid] = x * W3[tid * 2 + 1];
    __syncthreads();
    for (int o = 128; o > 0; o >>= 1) {
        if (tid < o) { sh0[tid] += sh0[tid + o]; sh1[tid] += sh1[tid + o]; }
        __syncthreads();
    }
    if (tid == 0) {
        out[row * 2 + 0] = sh0[0] + b3[0];
        out[row * 2 + 1] = sh1[0] + b3[1];
    }
}

// ---------------- launch ----------------------------------------------------
extern "C" void kernel_launch(void* const* d_in, const int* in_sizes, int n_in,
                              void* d_out, int out_size) {
    const float* hidden = (const float*)d_in[0];
    const int*   ids32  = (const int*)  d_in[1];
    const float* W1 = (const float*)d_in[2];
    const float* b1 = (const float*)d_in[3];
    const float* W2 = (const float*)d_in[4];
    const float* b2 = (const float*)d_in[5];
    const float* W3 = (const float*)d_in[6];
    const float* b3 = (const float*)d_in[7];
    float* out = (float*)d_out;

    void *p_sentb, *p_w1b, *p_x1b, *p_w2b, *p_x2p;
    cudaGetSymbolAddress(&p_sentb, g_sentb);
    cudaGetSymbolAddress(&p_w1b,   g_w1b);
    cudaGetSymbolAddress(&p_x1b,   g_x1b);
    cudaGetSymbolAddress(&p_w2b,   g_w2b);
    cudaGetSymbolAddress(&p_x2p,   g_x2p);

    // lazily created host-side objects (no device memory involved); the
    // enqueued work graph is identical on every call.
    static cudaStream_t s1 = nullptr;
    static cudaEvent_t eFork = nullptr, eJoin = nullptr;
    if (s1 == nullptr) {
        cudaStreamCreateWithFlags(&s1, cudaStreamNonBlocking);
        cudaEventCreateWithFlags(&eFork, cudaEventDisableTiming);
        cudaEventCreateWithFlags(&eJoin, cudaEventDisableTiming);
    }

    const int SMEM_DYN = 197632;          // GEMM: 3 x (32KB A + 32KB B) + slack
    const int SMEM_POOL = NBUF * CHUNK_BYTES;   // 48KB -> 4 CTAs/SM, single wave
    cudaFuncSetAttribute(mma_gemm<1>, cudaFuncAttributeMaxDynamicSharedMemorySize, SMEM_DYN);
    cudaFuncSetAttribute(mma_gemm<0>, cudaFuncAttributeMaxDynamicSharedMemorySize, SMEM_DYN);
    cudaFuncSetAttribute(pool_kernel, cudaFuncAttributeMaxDynamicSharedMemorySize, SMEM_POOL);

    // fork: weight conversions run on s1 concurrently with sep+pool
    cudaEventRecord(eFork, 0);
    cudaStreamWaitEvent(s1, eFork, 0);
    conv_w_kernel<<<dim3(F1 / 32, HH / 32), dim3(32, 8), 0, s1>>>(
        W1, (__half*)p_w1b, HH, F1);
    conv_w_kernel<<<dim3(F2 / 32, F1 / 32), dim3(32, 8), 0, s1>>>(
        W2, (__half*)p_w2b, F1, F2);
    cudaEventRecord(eJoin, s1);

    sep_scan_kernel<<<BB, 256>>>(ids32);
    pool_kernel<<<dim3(MS, BB), 192, SMEM_POOL>>>(hidden);

    // join before GEMM1 (covers GEMM2's W2 dependency as well)
    cudaStreamWaitEvent(0, eJoin, 0);

    // GEMM1: [512, 768] x [4096, 768]^T -> gelu -> fp16 x1  (6 stages)
    mma_gemm<1><<<dim3(F1 / 128, MROWS / 128, 1), 256, SMEM_DYN>>>(
        (const __half*)p_sentb, HH, (const __half*)p_w1b, HH,
        HH / 128, b1, nullptr, (__half*)p_x1b);

    // GEMM2: [512, 4096] x [256, 4096]^T, split-K=16 -> fp32 partials (2 stages)
    mma_gemm<0><<<dim3(F2 / 128, MROWS / 128, NSPLIT), 256, SMEM_DYN>>>(
        (const __half*)p_x1b, F1, (const __half*)p_w2b, F1,
        F1 / (128 * NSPLIT), nullptr, (float*)p_x2p, nullptr);

    reduce_head_kernel<<<MROWS, 256>>>(b2, W3, b3, out);
}

// round 15
// speedup vs baseline: 1.2713x; 1.2713x over previous
#include <cuda_runtime.h>
#include <cuda_fp16.h>
#include <math.h>
#include <stdint.h>

#define BB 8
#define SS 4096
#define HH 768
#define MS 64
#define F1 4096
#define F2 256
#define SEPTOK 2
#define MROWS 512          // BB*MS
#define NSPLIT 16
#define CHUNK_T 16                          // tokens per bulk chunk (R12 best)
#define CHUNK_BYTES (CHUNK_T * HH * 4)      // 49152
#define NBUF 2                              // pool smem ring depth

// ---------------- scratch (device globals; no allocation allowed) ----------
__device__ __align__(1024) __half g_sentb[MROWS * HH];    // A GEMM1, fp16
__device__ __align__(1024) __half g_w1b[F1 * HH];         // B GEMM1: W1^T fp16
__device__ __align__(1024) __half g_x1b[MROWS * F1];      // A GEMM2, fp16
__device__ __align__(1024) __half g_w2b[F2 * F1];         // B GEMM2: W2^T fp16
__device__ __align__(1024) float g_x2p[NSPLIT * MROWS * F2];   // split-K partials
__device__ int   g_sep_pos[BB][SS];
__device__ int   g_nsep[BB];

__device__ __forceinline__ float gelu_exact(float x) {
    return 0.5f * x * (1.0f + erff(x * 0.70710678118654752f));
}

__device__ __forceinline__ uint32_t smem_u32(const void* p) {
    uint32_t a;
    asm("{ .reg .u64 t; cvta.to.shared.u64 t, %1; cvt.u32.u64 %0, t; }" : "=r"(a) : "l"(p));
    return a;
}
__device__ __forceinline__ uint32_t sw128(uint32_t off) {
    return off ^ ((off >> 3) & 0x70);
}
__device__ __forceinline__ void cp_async16(uint32_t dst, const void* src) {
    asm volatile("cp.async.cg.shared.global [%0], [%1], 16;" :: "r"(dst), "l"(src) : "memory");
}
__device__ __forceinline__ void cp_commit() {
    asm volatile("cp.async.commit_group;" ::: "memory");
}
template<int N>
__device__ __forceinline__ void cp_waitg() {
    asm volatile("cp.async.wait_group %0;" :: "n"(N) : "memory");
}
__device__ __forceinline__ void ldsm_x4(uint32_t* r, uint32_t addr) {
    asm volatile("ldmatrix.sync.aligned.m8n8.x4.shared.b16 {%0,%1,%2,%3}, [%4];"
                 : "=r"(r[0]), "=r"(r[1]), "=r"(r[2]), "=r"(r[3]) : "r"(addr));
}
__device__ __forceinline__ void mma16816(float* d, const uint32_t* a, const uint32_t* b) {
    asm volatile(
        "mma.sync.aligned.m16n8k16.row.col.f32.f16.f16.f32 "
        "{%0,%1,%2,%3}, {%4,%5,%6,%7}, {%8,%9}, {%0,%1,%2,%3};"
        : "+f"(d[0]), "+f"(d[1]), "+f"(d[2]), "+f"(d[3])
        : "r"(a[0]), "r"(a[1]), "r"(a[2]), "r"(a[3]), "r"(b[0]), "r"(b[1]));
}

#define MBAR_INIT(a, c) \
    asm volatile("mbarrier.init.shared.b64 [%0], %1;" :: "r"(a), "r"(c) : "memory")
#define MBAR_EXPECT_TX(a, bytes) \
    asm volatile("mbarrier.arrive.expect_tx.shared.b64 _, [%0], %1;" :: "r"(a), "r"(bytes) : "memory")
#define MBAR_WAIT(mb, par) do {                                                        \
    uint32_t _m = (mb), _p = (par), _d;                                                \
    asm volatile("{\n\t.reg .pred p;\n\t"                                              \
        "mbarrier.try_wait.parity.acquire.cta.shared::cta.b64 p, [%1], %2;\n\t"        \
        "selp.b32 %0, 1, 0, p;\n\t}" : "=r"(_d) : "r"(_m), "r"(_p) : "memory");        \
    if (!_d) {                                                                         \
        asm volatile("{\n\t.reg .pred P1;\n\t"                                         \
            "WAIT_LOOP_%=:\n\t"                                                        \
            "mbarrier.try_wait.parity.acquire.cta.shared::cta.b64 P1, [%0], %1, 0x989680;\n\t" \
            "@P1 bra.uni WAIT_DONE_%=;\n\t"                                            \
            "bra.uni WAIT_LOOP_%=;\n\t"                                                \
            "WAIT_DONE_%=:\n\t}" :: "r"(_m), "r"(_p) : "memory");                      \
    }                                                                                  \
} while (0)

// segment bounds (reference semantics)
__device__ __forceinline__ void seg_bounds(int b, int s, int& t0, int& t1) {
    const int n = g_nsep[b];
    t0 = 0; t1 = 0;
    if (n == 0) {
        if (s == 0) { t0 = 0; t1 = SS; }
    } else if (s < n) {
        if (s == 0) { t0 = 0; t1 = g_sep_pos[b][0] + 1; }
        else        { t0 = g_sep_pos[b][s - 1] + 1; t1 = g_sep_pos[b][s]; }
    } else if (s == n) {
        t0 = g_sep_pos[b][n - 1] + 1; t1 = SS - 1;
    }
}

// ---------------- 1) sep scan (shuffle block scan) --------------------------
__global__ void sep_scan_kernel(const int* __restrict__ ids32) {
    const int b = blockIdx.x;
    const int tid = threadIdx.x;                  // 256
    const int stride = (ids32[1] == 0) ? 2 : 1;   // int64 vs int32 auto-detect
    const int* row = ids32 + (size_t)b * SS * stride;

    const int base = tid * 16;
    int c = 0;
    #pragma unroll
    for (int i = 0; i < 16; i++)
        if (row[(base + i) * stride] == SEPTOK) c++;

    const int lane = tid & 31, w = tid >> 5;
    int incl = c;
    #pragma unroll
    for (int o = 1; o < 32; o <<= 1) {
        int t = __shfl_up_sync(0xffffffffu, incl, o);
        if (lane >= o) incl += t;
    }
    __shared__ int wsum[8], woff[8];
    if (lane == 31) wsum[w] = incl;
    __syncthreads();
    if (tid == 0) {
        int a = 0;
        #pragma unroll
        for (int i = 0; i < 8; i++) { woff[i] = a; a += wsum[i]; }
        g_nsep[b] = a;
    }
    __syncthreads();

    int off = woff[w] + incl - c;
    for (int i = 0; i < 16; i++)
        if (row[(base + i) * stride] == SEPTOK)
            g_sep_pos[b][off++] = base + i;
}

// ---------------- 2) pooling via cp.async.bulk (TMA path) -------------------
// b_base splits the batch axis so the pipeline can start GEMM1 on half 0.
__global__ void pool_kernel(const float* __restrict__ hidden, int b_base) {
    const int s   = blockIdx.x;            // 0..63
    const int b   = b_base + blockIdx.y;   // half of 0..7
    const int tid = threadIdx.x;           // 192 (= HH/4)

    extern __shared__ __align__(16) char psm[];       // NBUF x CHUNK_BYTES
    __shared__ __align__(8) uint64_t mbar[NBUF];

    int t0, t1;
    seg_bounds(b, s, t0, t1);
    const int len = t1 - t0;
    const int nc  = (len + CHUNK_T - 1) / CHUNK_T;

    const uint32_t smBase = smem_u32(psm);
    const uint32_t mb     = smem_u32(&mbar[0]);

    if (tid < NBUF) MBAR_INIT(mb + tid * 8, 1);
    __syncthreads();

    const float* src0 = hidden + (size_t)b * SS * HH + (size_t)t0 * HH;

    auto issue = [&](int i) {   // tid==0 only
        const int ct = min(CHUNK_T, len - i * CHUNK_T);
        const uint32_t bytes = (uint32_t)ct * HH * 4;
        const int bi = i & (NBUF - 1);
        const uint32_t mbi = mb + (uint32_t)(bi * 8);
        MBAR_EXPECT_TX(mbi, bytes);
        asm volatile(
            "cp.async.bulk.shared::cluster.global.mbarrier::complete_tx::bytes "
            "[%0], [%1], %2, [%3];"
            :: "r"(smBase + (uint32_t)(bi * CHUNK_BYTES)),
               "l"(src0 + (size_t)i * CHUNK_T * HH), "r"(bytes), "r"(mbi)
            : "memory");
    };

    if (tid == 0) {
        #pragma unroll
        for (int i = 0; i < NBUF; i++)
            if (i < nc) issue(i);
    }

    float4 acc = make_float4(0.f, 0.f, 0.f, 0.f);
    for (int i = 0; i < nc; i++) {
        MBAR_WAIT(mb + (i & (NBUF - 1)) * 8, (i / NBUF) & 1);
        const int ct = min(CHUNK_T, len - i * CHUNK_T);
        const float4* buf = (const float4*)(psm + (i & (NBUF - 1)) * CHUNK_BYTES);
        for (int t = 0; t < ct; t++) {
            float4 v = buf[t * 192 + tid];
            acc.x += v.x; acc.y += v.y; acc.z += v.z; acc.w += v.w;
        }
        __syncthreads();                       // buffer free for reuse
        if (tid == 0 && i + NBUF < nc) issue(i + NBUF);
    }

    const float inv = (len > 0) ? (1.0f / (float)len) : 0.0f;
    const size_t rb = (size_t)(b * MS + s) * HH + tid * 4;
    *(__half2*)(&g_sentb[rb]) =
        __halves2half2(__float2half(acc.x * inv), __float2half(acc.y * inv));
    *(__half2*)(&g_sentb[rb + 2]) =
        __halves2half2(__float2half(acc.z * inv), __float2half(acc.w * inv));
}

// ---------------- 3) weight transpose, fp16 -------------------------------
// W: [K, N] row-major  ->  out: [N, K] fp16
__global__ void conv_w_kernel(const float* __restrict__ W, __half* __restrict__ out,
                              int K, int N) {
    __shared__ float t[32][33];
    const int n0 = blockIdx.x * 32, k0 = blockIdx.y * 32;
    const int tx = threadIdx.x, ty = threadIdx.y;   // 32 x 8
    #pragma unroll
    for (int i = 0; i < 4; i++)
        t[ty + i * 8][tx] = W[(size_t)(k0 + ty + i * 8) * N + n0 + tx];
    __syncthreads();
    #pragma unroll
    for (int i = 0; i < 4; i++) {
        const int nn = n0 + ty + i * 8;
        out[(size_t)nn * K + k0 + tx] = __float2half(t[tx][ty + i * 8]);
    }
}

// ---------------- 4) mma.sync fp16 GEMM, 128x128 tile, K staged 128 ---------
// A: [M, lda] K-major fp16.  B: [N, ldb] K-major fp16 (B^T).  mBase offsets
// the M tiles so the pipeline can run per-half.
// EPI==1: D + bias -> GELU -> fp16 x1.  EPI==0: fp32 split-K partials.
template<int EPI>
__global__ __launch_bounds__(256)
void mma_gemm(const __half* __restrict__ A, int lda,
              const __half* __restrict__ Bm, int ldb,
              int nStages, int mBase,
              const float* __restrict__ bias,
              float* __restrict__ Cout,
              __half* __restrict__ OutB)
{
    extern __shared__ char dsm_raw[];
    char* dsm = (char*)(((uintptr_t)dsm_raw + 1023) & ~(uintptr_t)1023);

    const int tid  = threadIdx.x;
    const int wid  = tid >> 5, lane = tid & 31;
    const int m0   = mBase + blockIdx.y * 128;
    const int n0   = blockIdx.x * 128;
    const int z    = blockIdx.z;
    const int ks0  = z * nStages * 128;

    const uint32_t smBase = smem_u32(dsm);

    auto load_stage = [&](int buf, int s) {
        const int ko = ks0 + s * 128;
        const uint32_t dA = smBase + buf * 32768;
        const uint32_t dB = smBase + 98304 + buf * 32768;
        #pragma unroll
        for (int sub = 0; sub < 2; sub++) {
            const __half* Ag = A  + (size_t)m0 * lda + ko + sub * 64;
            const __half* Bg = Bm + (size_t)n0 * ldb + ko + sub * 64;
            #pragma unroll
            for (int i = 0; i < 4; i++) {
                const int ch = tid + i * 256;     // 1024 16B chunks / sub-tile
                const int r = ch >> 3, c = ch & 7;
                const uint32_t sw = sw128((uint32_t)(r * 128 + c * 16)) + sub * 16384;
                cp_async16(dA + sw, Ag + (size_t)r * lda + c * 8);
                cp_async16(dB + sw, Bg + (size_t)r * ldb + c * 8);
            }
        }
    };

    // ---- warp/lane fragment geometry
    const int wm0 = (wid & 3) * 32;
    const int wn0 = (wid >> 2) * 64;
    const int grp = lane >> 3, rowin = lane & 7;
    const int a_mloc = rowin + ((grp & 1) << 3);
    const int a_koff = (grp >> 1) << 4;
    const int b_nloc = rowin + ((grp >> 1) << 3);
    const int b_koff = (grp & 1) << 4;

    float acc[2][8][4];
    #pragma unroll
    for (int mt = 0; mt < 2; mt++)
        #pragma unroll
        for (int nt = 0; nt < 8; nt++)
            #pragma unroll
            for (int q = 0; q < 4; q++) acc[mt][nt][q] = 0.f;

    load_stage(0, 0);
    cp_commit();
    if (nStages > 1) { load_stage(1, 1); cp_commit(); }

    int buf = 0;
    for (int s = 0; s < nStages; s++) {
        if (s + 1 < nStages) cp_waitg<1>(); else cp_waitg<0>();
        __syncthreads();

        #pragma unroll
        for (int sub = 0; sub < 2; sub++) {
            const uint32_t uA = smBase + buf * 32768 + sub * 16384;
            const uint32_t uB = smBase + 98304 + buf * 32768 + sub * 16384;
            const uint32_t aRow[2] = {
                uA + (uint32_t)((wm0 + a_mloc) * 128),
                uA + (uint32_t)((wm0 + 16 + a_mloc) * 128) };
            const uint32_t aXor = (uint32_t)(((wm0 + a_mloc) & 7) << 4);
            const uint32_t bXor = (uint32_t)(((wn0 + b_nloc) & 7) << 4);

            #pragma unroll
            for (int kk = 0; kk < 4; kk++) {
                uint32_t afr[2][4];
                #pragma unroll
                for (int mt = 0; mt < 2; mt++)
                    ldsm_x4(afr[mt], aRow[mt] + (((uint32_t)(kk * 32 + a_koff)) ^ aXor));

                uint32_t bfr[8][2];
                #pragma unroll
                for (int p = 0; p < 4; p++) {
                    uint32_t r4[4];
                    const uint32_t bRow = uB + (uint32_t)((wn0 + p * 16 + b_nloc) * 128);
                    ldsm_x4(r4, bRow + (((uint32_t)(kk * 32 + b_koff)) ^ bXor));
                    bfr[2 * p][0] = r4[0]; bfr[2 * p][1] = r4[1];
                    bfr[2 * p + 1][0] = r4[2]; bfr[2 * p + 1][1] = r4[3];
                }

                #pragma unroll
                for (int mt = 0; mt < 2; mt++)
                    #pragma unroll
                    for (int nt = 0; nt < 8; nt++)
                        mma16816(acc[mt][nt], afr[mt], bfr[nt]);
            }
        }

        if (s + 2 < nStages) { load_stage((s + 2) % 3, s + 2); cp_commit(); }
        buf = (buf + 1) % 3;
    }

    // ---- epilogue
    #pragma unroll
    for (int mt = 0; mt < 2; mt++) {
        const int rA = m0 + wm0 + mt * 16 + (lane >> 2);
        #pragma unroll
        for (int half = 0; half < 2; half++) {
            const int r = rA + half * 8;
            if (EPI == 1) {
                const size_t rowbase = (size_t)r * F1;
                #pragma unroll
                for (int nt = 0; nt < 8; nt++) {
                    const int f = n0 + wn0 + nt * 8 + (lane & 3) * 2;
                    float v0 = gelu_exact(acc[mt][nt][2 * half]     + __ldg(&bias[f]));
                    float v1 = gelu_exact(acc[mt][nt][2 * half + 1] + __ldg(&bias[f + 1]));
                    *(__half2*)(&OutB[rowbase + f]) =
                        __halves2half2(__float2half(v0), __float2half(v1));
                }
            } else {
                float* Cp = Cout + (size_t)z * MROWS * F2 + (size_t)r * F2;
                #pragma unroll
                for (int nt = 0; nt < 8; nt++) {
                    const int f = n0 + wn0 + nt * 8 + (lane & 3) * 2;
                    float2 v; v.x = acc[mt][nt][2 * half]; v.y = acc[mt][nt][2 * half + 1];
                    *(float2*)(Cp + f) = v;
                }
            }
        }
    }
}

// ---------------- 5) fused split-K reduce + bias + GELU + head --------------
__global__ void reduce_head_kernel(const float* __restrict__ b2,
                                   const float* __restrict__ W3,
                                   const float* __restrict__ b3,
                                   float* __restrict__ out, int rowBase) {
    const int row = rowBase + blockIdx.x;
    const int tid = threadIdx.x;  // 256
    const int idx = row * F2 + tid;
    float s = 0.f;
    #pragma unroll
    for (int i = 0; i < NSPLIT; i++) s += g_x2p[(size_t)i * MROWS * F2 + idx];
    const float x = gelu_exact(s + b2[tid]);

    __shared__ float sh0[256];
    __shared__ float sh1[256];
    sh0[tid] = x * W3[tid * 2 + 0];
    sh1[tid] = x * W3[tid * 2 + 1];
    __syncthreads();
    for (int o = 128; o > 0; o >>= 1) {
        if (tid < o) { sh0[tid] += sh0[tid + o]; sh1[tid] += sh1[tid + o]; }
        __syncthreads();
    }
    if (tid == 0) {
        out[row * 2 + 0] = sh0[0] + b3[0];
        out[row * 2 + 1] = sh1[0] + b3[1];
    }
}

// ---------------- launch ----------------------------------------------------
extern "C" void kernel_launch(void* const* d_in, const int* in_sizes, int n_in,
                              void* d_out, int out_size) {
    const float* hidden = (const float*)d_in[0];
    const int*   ids32  = (const int*)  d_in[1];
    const float* W1 = (const float*)d_in[2];
    const float* b1 = (const float*)d_in[3];
    const float* W2 = (const float*)d_in[4];
    const float* b2 = (const float*)d_in[5];
    const float* W3 = (const float*)d_in[6];
    const float* b3 = (const float*)d_in[7];
    float* out = (float*)d_out;

    void *p_sentb, *p_w1b, *p_x1b, *p_w2b, *p_x2p;
    cudaGetSymbolAddress(&p_sentb, g_sentb);
    cudaGetSymbolAddress(&p_w1b,   g_w1b);
    cudaGetSymbolAddress(&p_x1b,   g_x1b);
    cudaGetSymbolAddress(&p_w2b,   g_w2b);
    cudaGetSymbolAddress(&p_x2p,   g_x2p);

    // lazily created host-side objects (no device memory involved)
    static cudaStream_t s1 = nullptr, s2 = nullptr;
    static cudaEvent_t eFork = nullptr, eW = nullptr, eP0 = nullptr, eC0 = nullptr;
    if (s1 == nullptr) {
        cudaStreamCreateWithFlags(&s1, cudaStreamNonBlocking);
        cudaStreamCreateWithFlags(&s2, cudaStreamNonBlocking);
        cudaEventCreateWithFlags(&eFork, cudaEventDisableTiming);
        cudaEventCreateWithFlags(&eW,    cudaEventDisableTiming);
        cudaEventCreateWithFlags(&eP0,   cudaEventDisableTiming);
        cudaEventCreateWithFlags(&eC0,   cudaEventDisableTiming);
    }

    const int SMEM_DYN  = 197632;               // GEMM: 3 x 64KB + slack
    const int SMEM_POOL = NBUF * CHUNK_BYTES;   // 96KB (R12 best config)
    cudaFuncSetAttribute(mma_gemm<1>, cudaFuncAttributeMaxDynamicSharedMemorySize, SMEM_DYN);
    cudaFuncSetAttribute(mma_gemm<0>, cudaFuncAttributeMaxDynamicSharedMemorySize, SMEM_DYN);
    cudaFuncSetAttribute(pool_kernel, cudaFuncAttributeMaxDynamicSharedMemorySize, SMEM_POOL);

    // fork: weight conversions on s1
    cudaEventRecord(eFork, 0);
    cudaStreamWaitEvent(s1, eFork, 0);
    conv_w_kernel<<<dim3(F1 / 32, HH / 32), dim3(32, 8), 0, s1>>>(
        W1, (__half*)p_w1b, HH, F1);
    conv_w_kernel<<<dim3(F2 / 32, F1 / 32), dim3(32, 8), 0, s1>>>(
        W2, (__half*)p_w2b, F1, F2);
    cudaEventRecord(eW, s1);

    // main stream: sep scan, then pool half 0 (batches 0-3)
    sep_scan_kernel<<<BB, 256>>>(ids32);
    pool_kernel<<<dim3(MS, BB / 2), 192, SMEM_POOL>>>(hidden, 0);
    cudaEventRecord(eP0, 0);
    // pool half 1 (batches 4-7) continues on the main stream
    pool_kernel<<<dim3(MS, BB / 2), 192, SMEM_POOL>>>(hidden, BB / 2);

    // s2: half-0 compute chain overlaps pool half 1
    cudaStreamWaitEvent(s2, eP0, 0);
    cudaStreamWaitEvent(s2, eW, 0);
    mma_gemm<1><<<dim3(F1 / 128, 2, 1), 256, SMEM_DYN, s2>>>(
        (const __half*)p_sentb, HH, (const __half*)p_w1b, HH,
        HH / 128, 0, b1, nullptr, (__half*)p_x1b);
    mma_gemm<0><<<dim3(F2 / 128, 2, NSPLIT), 256, SMEM_DYN, s2>>>(
        (const __half*)p_x1b, F1, (const __half*)p_w2b, F1,
        F1 / (128 * NSPLIT), 0, nullptr, (float*)p_x2p, nullptr);
    reduce_head_kernel<<<MROWS / 2, 256, 0, s2>>>(b2, W3, b3, out, 0);
    cudaEventRecord(eC0, s2);

    // main stream: half-1 compute chain after pool half 1
    cudaStreamWaitEvent(0, eW, 0);
    mma_gemm<1><<<dim3(F1 / 128, 2, 1), 256, SMEM_DYN>>>(
        (const __half*)p_sentb, HH, (const __half*)p_w1b, HH,
        HH / 128, 256, b1, nullptr, (__half*)p_x1b);
    mma_gemm<0><<<dim3(F2 / 128, 2, NSPLIT), 256, SMEM_DYN>>>(
        (const __half*)p_x1b, F1, (const __half*)p_w2b, F1,
        F1 / (128 * NSPLIT), 256, nullptr, (float*)p_x2p, nullptr);
    reduce_head_kernel<<<MROWS / 2, 256>>>(b2, W3, b3, out, MROWS / 2);

    // join half-0 chain back into the main stream
    cudaStreamWaitEvent(0, eC0, 0);
}